// round 2
// baseline (speedup 1.0000x reference)
#include <cuda_runtime.h>
#include <math.h>

// Problem constants (fixed by the reference)
#define NNODES   100000
#define NEDGES   1600000
#define F_IN     128
#define F_HID    64
#define N_GRAPHS 128

// Scratch (static __device__ arrays; no allocation allowed)
__device__ float g_deg[NNODES];
__device__ float g_dis[NNODES];
__device__ float g_bufA[(size_t)NNODES * F_HID]; // GEMM outputs (pre-aggregate)
__device__ float g_bufB[(size_t)NNODES * F_HID]; // aggregated / activated features
__device__ float g_pool[N_GRAPHS * F_HID];
__device__ float g_cnt[N_GRAPHS];

// ---------------------------------------------------------------------------
// vector reduction helper: red.global.add.v4.f32 (sm_90+)
// ---------------------------------------------------------------------------
__device__ __forceinline__ void red_add_v4(float* addr, float4 v) {
    asm volatile("red.global.add.v4.f32 [%0], {%1, %2, %3, %4};"
                 :: "l"(addr), "f"(v.x), "f"(v.y), "f"(v.z), "f"(v.w)
                 : "memory");
}

// ---------------------------------------------------------------------------
// degree / normalization
// ---------------------------------------------------------------------------
__global__ void k_init_deg(int n) {
    int i = blockIdx.x * blockDim.x + threadIdx.x;
    if (i < n) g_deg[i] = 1.0f; // self loop
}

__global__ void k_edge_deg(const int* __restrict__ dst, int nE) {
    int e = blockIdx.x * blockDim.x + threadIdx.x;
    if (e < nE) atomicAdd(&g_deg[dst[e]], 1.0f);
}

__global__ void k_dis(int n) {
    int i = blockIdx.x * blockDim.x + threadIdx.x;
    if (i < n) g_dis[i] = rsqrtf(g_deg[i]); // deg >= 1 always (self loop)
}

// ---------------------------------------------------------------------------
// GEMM: H[n, 64] = X[n, K] @ W[K, 64]
// block = 256 threads, 8 node-rows per block, each thread computes 2 rows x 1 col
// ---------------------------------------------------------------------------
template <int K, bool FROM_BUFB>
__global__ void k_gemm(const float* __restrict__ Xin, const float* __restrict__ W,
                       int n) {
    __shared__ float Ws[K * 64];
    __shared__ float xs[8 * K];

    const float* X = FROM_BUFB ? g_bufB : Xin;

    for (int i = threadIdx.x; i < K * 64; i += 256) Ws[i] = W[i];

    int nodeBase = blockIdx.x * 8;
    for (int i = threadIdx.x; i < 8 * K; i += 256) {
        int nn = nodeBase + i / K;
        xs[i] = (nn < n) ? X[(size_t)nn * K + (i % K)] : 0.0f;
    }
    __syncthreads();

    int j = threadIdx.x & 63;        // output feature
    int g = threadIdx.x >> 6;        // 0..3 -> node pair
    const float* x0 = &xs[(2 * g) * K];
    const float* x1 = &xs[(2 * g + 1) * K];

    float acc0 = 0.0f, acc1 = 0.0f;
#pragma unroll 16
    for (int k = 0; k < K; k++) {
        float w = Ws[k * 64 + j];
        acc0 = fmaf(x0[k], w, acc0);
        acc1 = fmaf(x1[k], w, acc1);
    }

    int n0 = nodeBase + 2 * g;
    int n1 = n0 + 1;
    if (n0 < n) g_bufA[(size_t)n0 * 64 + j] = acc0;
    if (n1 < n) g_bufA[(size_t)n1 * 64 + j] = acc1;
}

// ---------------------------------------------------------------------------
// self-loop init: bufB[i] = bufA[i] * dis[i]^2   (norm of self-loop = 1/deg)
// one thread per (node, float4)
// ---------------------------------------------------------------------------
__global__ void k_selfloop(int n) {
    int idx = blockIdx.x * blockDim.x + threadIdx.x;
    int i = idx >> 4, q = idx & 15;
    if (i >= n) return;
    float w = g_dis[i];
    w = w * w;
    float4 v = ((const float4*)(g_bufA + (size_t)i * 64))[q];
    v.x *= w; v.y *= w; v.z *= w; v.w *= w;
    ((float4*)(g_bufB + (size_t)i * 64))[q] = v;
}

// ---------------------------------------------------------------------------
// edge aggregation: bufB[dst] += bufA[src] * dis[src]*dis[dst]
// 16 threads per edge, vector reductions
// ---------------------------------------------------------------------------
__global__ void k_agg(const int* __restrict__ src,
                      const int* __restrict__ dst, int nE) {
    int idx = blockIdx.x * blockDim.x + threadIdx.x;
    int e = idx >> 4, q = idx & 15;
    if (e >= nE) return;
    int s = src[e];
    int d = dst[e];
    float w = g_dis[s] * g_dis[d];
    float4 v = ((const float4*)(g_bufA + (size_t)s * 64))[q];
    v.x *= w; v.y *= w; v.z *= w; v.w *= w;
    red_add_v4(g_bufB + (size_t)d * 64 + q * 4, v);
}

// ---------------------------------------------------------------------------
// bufB = relu(bufB + b)   in place
// ---------------------------------------------------------------------------
__global__ void k_relu_bias(const float* __restrict__ b, int n) {
    int idx = blockIdx.x * blockDim.x + threadIdx.x;
    int i = idx >> 4, q = idx & 15;
    if (i >= n) return;
    float4 bb = ((const float4*)b)[q];
    float4 v = ((float4*)(g_bufB + (size_t)i * 64))[q];
    v.x = fmaxf(v.x + bb.x, 0.0f);
    v.y = fmaxf(v.y + bb.y, 0.0f);
    v.z = fmaxf(v.z + bb.z, 0.0f);
    v.w = fmaxf(v.w + bb.w, 0.0f);
    ((float4*)(g_bufB + (size_t)i * 64))[q] = v;
}

// ---------------------------------------------------------------------------
// pooling
// ---------------------------------------------------------------------------
__global__ void k_pool_zero() {
    int i = blockIdx.x * blockDim.x + threadIdx.x;
    if (i < N_GRAPHS * F_HID) g_pool[i] = 0.0f;
    if (i < N_GRAPHS) g_cnt[i] = 0.0f;
}

__global__ void k_pool_acc(const int* __restrict__ batch, int n) {
    int idx = blockIdx.x * blockDim.x + threadIdx.x;
    int i = idx >> 4, q = idx & 15;
    if (i >= n) return;
    int g = batch[i];
    float4 v = ((const float4*)(g_bufB + (size_t)i * 64))[q];
    red_add_v4(g_pool + g * 64 + q * 4, v);
    if (q == 0) atomicAdd(&g_cnt[g], 1.0f);
}

// ---------------------------------------------------------------------------
// final: out[g, c] = (pool[g,:] / max(cnt,1)) @ Wf + bf
// ---------------------------------------------------------------------------
__global__ void k_final(const float* __restrict__ Wf, const float* __restrict__ bf,
                        float* __restrict__ out) {
    int t = threadIdx.x;
    if (t >= N_GRAPHS * 2) return;
    int g = t >> 1, c = t & 1;
    float acc = 0.0f;
#pragma unroll
    for (int j = 0; j < F_HID; j++)
        acc = fmaf(g_pool[g * 64 + j], Wf[j * 2 + c], acc);
    float cnt = fmaxf(g_cnt[g], 1.0f);
    out[g * 2 + c] = acc / cnt + bf[c];
}

// ---------------------------------------------------------------------------
// launch
// ---------------------------------------------------------------------------
extern "C" void kernel_launch(void* const* d_in, const int* in_sizes, int n_in,
                              void* d_out, int out_size) {
    const float* x    = (const float*)d_in[0];
    const int*   ei   = (const int*)d_in[1];  // [2, E] delivered as int32
    const int*   batch= (const int*)d_in[2];
    const float* W1   = (const float*)d_in[3];
    const float* b1   = (const float*)d_in[4];
    const float* W2   = (const float*)d_in[5];
    const float* b2   = (const float*)d_in[6];
    const float* Wf   = (const float*)d_in[7];
    const float* bf   = (const float*)d_in[8];
    float* out = (float*)d_out;

    int n  = in_sizes[0] / F_IN;       // 100000
    int nE = in_sizes[1] / 2;          // 1600000
    const int* src = ei;
    const int* dst = ei + nE;

    const int T = 256;
    int gN    = (n + T - 1) / T;
    int gE    = (nE + T - 1) / T;
    int gN16  = (int)(((size_t)n * 16 + T - 1) / T);
    int gE16  = (int)(((size_t)nE * 16 + T - 1) / T);
    int gGemm = (n + 7) / 8;

    // degree + normalization
    k_init_deg<<<gN, T>>>(n);
    k_edge_deg<<<gE, T>>>(dst, nE);
    k_dis<<<gN, T>>>(n);

    // layer 1
    k_gemm<F_IN, false><<<gGemm, T>>>(x, W1, n);
    k_selfloop<<<gN16, T>>>(n);
    k_agg<<<gE16, T>>>(src, dst, nE);
    k_relu_bias<<<gN16, T>>>(b1, n);

    // layer 2
    k_gemm<F_HID, true><<<gGemm, T>>>(nullptr, W2, n);
    k_selfloop<<<gN16, T>>>(n);
    k_agg<<<gE16, T>>>(src, dst, nE);
    k_relu_bias<<<gN16, T>>>(b2, n);

    // pooling + classifier
    k_pool_zero<<<(N_GRAPHS * F_HID + T - 1) / T, T>>>();
    k_pool_acc<<<gN16, T>>>(batch, n);
    k_final<<<1, T>>>(Wf, bf, out);
}

// round 3
// speedup vs baseline: 1.2475x; 1.2475x over previous
#include <cuda_runtime.h>
#include <math.h>

#define NNODES   100000
#define NEDGES   1600000
#define F_IN     128
#define F_HID    64
#define N_GRAPHS 128

__device__ float g_deg[NNODES];
__device__ float g_dis[NNODES];
__device__ float g_bufA[(size_t)NNODES * F_HID]; // GEMM outputs (pre-aggregate)
__device__ float g_bufB[(size_t)NNODES * F_HID]; // aggregated features
__device__ float g_pool[N_GRAPHS * F_HID];
__device__ float g_cnt[N_GRAPHS];

__device__ __forceinline__ void red_add_v4(float* addr, float4 v) {
    asm volatile("red.global.add.v4.f32 [%0], {%1, %2, %3, %4};"
                 :: "l"(addr), "f"(v.x), "f"(v.y), "f"(v.z), "f"(v.w)
                 : "memory");
}

// ---------------------------------------------------------------------------
// init: deg=1 (self loop), pool=0, cnt=0
// ---------------------------------------------------------------------------
__global__ void k_init(int n) {
    int i = blockIdx.x * blockDim.x + threadIdx.x;
    if (i < n) g_deg[i] = 1.0f;
    if (i < N_GRAPHS * F_HID) g_pool[i] = 0.0f;
    if (i < N_GRAPHS) g_cnt[i] = 0.0f;
}

__global__ void k_edge_deg(const int* __restrict__ dst, int nE) {
    int e = blockIdx.x * blockDim.x + threadIdx.x;
    if (e < nE) atomicAdd(&g_deg[dst[e]], 1.0f);
}

__global__ void k_dis(int n) {
    int i = blockIdx.x * blockDim.x + threadIdx.x;
    if (i < n) g_dis[i] = rsqrtf(g_deg[i]);
}

// ---------------------------------------------------------------------------
// GEMM: bufA[n,64] = act(X[n,K]) @ W[K,64];  bufB = bufA * dis^2 (fused selfloop)
// act = relu(x + bias) when BIASED (layer-2 input), else identity.
// Block: 256 threads, tile 32 nodes x 64 cols, each thread 2 nodes x 4 cols.
// ---------------------------------------------------------------------------
template <int K, bool FROM_BUFB, bool BIASED>
__global__ void k_gemm(const float* __restrict__ Xin, const float* __restrict__ W,
                       const float* __restrict__ bias, int n) {
    __shared__ float Ws[K * 64];          // row-major [K][64]
    __shared__ float xs[32 * (K + 1)];    // [node][k], stride K+1 (bank-conflict pad)

    const float* X = FROM_BUFB ? g_bufB : Xin;

    // load W (float4, coalesced)
    {
        const float4* Wg = (const float4*)W;
        float4* Wsm = (float4*)Ws;
#pragma unroll
        for (int i = threadIdx.x; i < K * 16; i += 256) Wsm[i] = Wg[i];
    }

    // load X tile (scalar, coalesced reads; act applied on load)
    int nodeBase = blockIdx.x * 32;
#pragma unroll
    for (int t = 0; t < 32 * K / 256; t++) {
        int idx = t * 256 + threadIdx.x;
        int nn = idx / K, kk = idx % K;
        int node = nodeBase + nn;
        float v = 0.0f;
        if (node < n) {
            v = X[(size_t)node * K + kk];
            if (BIASED) v = fmaxf(v + bias[kk], 0.0f);
        }
        xs[nn * (K + 1) + kk] = v;
    }
    __syncthreads();

    int jx = threadIdx.x & 15;        // col quad: cols 4*jx .. 4*jx+3
    int ny = threadIdx.x >> 4;        // node pair: nodes 2*ny, 2*ny+1
    const float* x0 = &xs[(2 * ny) * (K + 1)];
    const float* x1 = &xs[(2 * ny + 1) * (K + 1)];
    const float4* W4 = (const float4*)Ws;

    float4 a0 = {0,0,0,0}, a1 = {0,0,0,0};
#pragma unroll 8
    for (int k = 0; k < K; k++) {
        float4 w = W4[k * 16 + jx];
        float v0 = x0[k], v1 = x1[k];
        a0.x = fmaf(v0, w.x, a0.x); a0.y = fmaf(v0, w.y, a0.y);
        a0.z = fmaf(v0, w.z, a0.z); a0.w = fmaf(v0, w.w, a0.w);
        a1.x = fmaf(v1, w.x, a1.x); a1.y = fmaf(v1, w.y, a1.y);
        a1.z = fmaf(v1, w.z, a1.z); a1.w = fmaf(v1, w.w, a1.w);
    }

    int n0 = nodeBase + 2 * ny;
    int n1 = n0 + 1;
    if (n0 < n) {
        ((float4*)(g_bufA + (size_t)n0 * 64))[jx] = a0;
        float s = g_dis[n0]; s *= s;
        float4 b = {a0.x * s, a0.y * s, a0.z * s, a0.w * s};
        ((float4*)(g_bufB + (size_t)n0 * 64))[jx] = b;
    }
    if (n1 < n) {
        ((float4*)(g_bufA + (size_t)n1 * 64))[jx] = a1;
        float s = g_dis[n1]; s *= s;
        float4 b = {a1.x * s, a1.y * s, a1.z * s, a1.w * s};
        ((float4*)(g_bufB + (size_t)n1 * 64))[jx] = b;
    }
}

// ---------------------------------------------------------------------------
// edge aggregation: bufB[dst] += bufA[src] * dis[src]*dis[dst]
// 16 threads per edge, vector reductions
// ---------------------------------------------------------------------------
__global__ void k_agg(const int* __restrict__ src,
                      const int* __restrict__ dst, int nE) {
    int idx = blockIdx.x * blockDim.x + threadIdx.x;
    int e = idx >> 4, q = idx & 15;
    if (e >= nE) return;
    int s = src[e];
    int d = dst[e];
    float w = g_dis[s] * g_dis[d];
    float4 v = ((const float4*)(g_bufA + (size_t)s * 64))[q];
    v.x *= w; v.y *= w; v.z *= w; v.w *= w;
    red_add_v4(g_bufB + (size_t)d * 64 + q * 4, v);
}

// ---------------------------------------------------------------------------
// pooling: pool[batch[i]] += relu(bufB[i] + b2)    (relu+bias fused on load)
// ---------------------------------------------------------------------------
__global__ void k_pool_acc(const int* __restrict__ batch,
                           const float* __restrict__ b2, int n) {
    int idx = blockIdx.x * blockDim.x + threadIdx.x;
    int i = idx >> 4, q = idx & 15;
    if (i >= n) return;
    int g = batch[i];
    float4 bb = ((const float4*)b2)[q];
    float4 v = ((const float4*)(g_bufB + (size_t)i * 64))[q];
    v.x = fmaxf(v.x + bb.x, 0.0f);
    v.y = fmaxf(v.y + bb.y, 0.0f);
    v.z = fmaxf(v.z + bb.z, 0.0f);
    v.w = fmaxf(v.w + bb.w, 0.0f);
    red_add_v4(g_pool + g * 64 + q * 4, v);
    if (q == 0) atomicAdd(&g_cnt[g], 1.0f);
}

// ---------------------------------------------------------------------------
// final: out[g, c] = (pool[g,:] / max(cnt,1)) @ Wf + bf
// ---------------------------------------------------------------------------
__global__ void k_final(const float* __restrict__ Wf, const float* __restrict__ bf,
                        float* __restrict__ out) {
    int t = threadIdx.x;
    if (t >= N_GRAPHS * 2) return;
    int g = t >> 1, c = t & 1;
    float acc = 0.0f;
#pragma unroll
    for (int j = 0; j < F_HID; j++)
        acc = fmaf(g_pool[g * 64 + j], Wf[j * 2 + c], acc);
    float cnt = fmaxf(g_cnt[g], 1.0f);
    out[g * 2 + c] = acc / cnt + bf[c];
}

// ---------------------------------------------------------------------------
extern "C" void kernel_launch(void* const* d_in, const int* in_sizes, int n_in,
                              void* d_out, int out_size) {
    const float* x    = (const float*)d_in[0];
    const int*   ei   = (const int*)d_in[1];  // [2, E] int32
    const int*   batch= (const int*)d_in[2];
    const float* W1   = (const float*)d_in[3];
    const float* b1   = (const float*)d_in[4];
    const float* W2   = (const float*)d_in[5];
    const float* b2   = (const float*)d_in[6];
    const float* Wf   = (const float*)d_in[7];
    const float* bf   = (const float*)d_in[8];
    float* out = (float*)d_out;

    int n  = in_sizes[0] / F_IN;       // 100000
    int nE = in_sizes[1] / 2;          // 1600000
    const int* src = ei;
    const int* dst = ei + nE;

    const int T = 256;
    int gN    = (n + T - 1) / T;
    int gE    = (nE + T - 1) / T;
    int gN16  = (int)(((size_t)n * 16 + T - 1) / T);
    int gE16  = (int)(((size_t)nE * 16 + T - 1) / T);
    int gGemm = (n + 31) / 32;

    // degree + normalization (+ zero pool accumulators)
    k_init<<<gN, T>>>(n);
    k_edge_deg<<<gE, T>>>(dst, nE);
    k_dis<<<gN, T>>>(n);

    // layer 1: bufA = x@W1, bufB = bufA*dis^2, then scatter
    k_gemm<F_IN, false, false><<<gGemm, T>>>(x, W1, nullptr, n);
    k_agg<<<gE16, T>>>(src, dst, nE);

    // layer 2: bufA = relu(bufB+b1)@W2, bufB = bufA*dis^2, then scatter
    k_gemm<F_HID, true, true><<<gGemm, T>>>(nullptr, W2, b1, n);
    k_agg<<<gE16, T>>>(src, dst, nE);

    // pooling (relu+b2 fused) + classifier
    k_pool_acc<<<gN16, T>>>(batch, b2, n);
    k_final<<<1, T>>>(Wf, bf, out);
}

// round 4
// speedup vs baseline: 1.3165x; 1.0553x over previous
#include <cuda_runtime.h>
#include <math.h>

#define NNODES   100000
#define NEDGES   1600000
#define F_IN     128
#define F_HID    64
#define N_GRAPHS 128

// scratch
__device__ int   g_count[NNODES];        // in-degree (without self loop)
__device__ int   g_rowptr[NNODES + 1];   // CSR row pointers
__device__ int   g_fill[NNODES];         // running fill cursors
__device__ int   g_csrsrc[NEDGES];       // CSR column (source node) array
__device__ float g_dis[NNODES];          // deg^{-1/2}
__device__ float g_bufA[(size_t)NNODES * F_HID]; // GEMM output (pre-aggregate)
__device__ float g_bufB[(size_t)NNODES * F_HID]; // aggregated features
__device__ float g_pool[N_GRAPHS * F_HID];
__device__ float g_cnt[N_GRAPHS];

__device__ __forceinline__ void red_add_v4(float* addr, float4 v) {
    asm volatile("red.global.add.v4.f32 [%0], {%1, %2, %3, %4};"
                 :: "l"(addr), "f"(v.x), "f"(v.y), "f"(v.z), "f"(v.w)
                 : "memory");
}

// ---------------------------------------------------------------------------
// zero counters / pool accumulators
// ---------------------------------------------------------------------------
__global__ void k_zero(int n) {
    int i = blockIdx.x * blockDim.x + threadIdx.x;
    if (i < n) g_count[i] = 0;
    if (i < N_GRAPHS * F_HID) g_pool[i] = 0.0f;
    if (i < N_GRAPHS) g_cnt[i] = 0.0f;
}

__global__ void k_histo(const int* __restrict__ dst, int nE) {
    int e = blockIdx.x * blockDim.x + threadIdx.x;
    if (e < nE) atomicAdd(&g_count[dst[e]], 1);
}

// ---------------------------------------------------------------------------
// single-block exclusive prefix scan of g_count -> g_rowptr / g_fill,
// plus dis = rsqrt(count+1). Processes 4096 values per tile via int4.
// ---------------------------------------------------------------------------
__global__ void k_scan(int n) {
    __shared__ int warpTot[32];
    __shared__ int warpOff[32];
    __shared__ int tileTot;
    __shared__ int carry_s;
    int tid = threadIdx.x, lane = tid & 31, wid = tid >> 5;
    if (tid == 0) carry_s = 0;
    __syncthreads();

    int n4 = n >> 2; // n is a multiple of 4 (100000)
    for (int base = 0; base < n4; base += 1024) {
        int i4 = base + tid;
        int4 c = {0, 0, 0, 0};
        if (i4 < n4) c = ((const int4*)g_count)[i4];
        int v = c.x + c.y + c.z + c.w;
        int x = v;
#pragma unroll
        for (int d = 1; d < 32; d <<= 1) {
            int y = __shfl_up_sync(0xffffffffu, x, d);
            if (lane >= d) x += y;
        }
        if (lane == 31) warpTot[wid] = x;
        __syncthreads();
        if (wid == 0) {
            int s = warpTot[lane];
            int t2 = s;
#pragma unroll
            for (int d = 1; d < 32; d <<= 1) {
                int y = __shfl_up_sync(0xffffffffu, t2, d);
                if (lane >= d) t2 += y;
            }
            warpOff[lane] = t2 - s;
            if (lane == 31) tileTot = t2;
        }
        __syncthreads();
        if (i4 < n4) {
            int excl = carry_s + warpOff[wid] + (x - v);
            int i = i4 * 4;
            g_rowptr[i + 0] = excl;
            g_rowptr[i + 1] = excl + c.x;
            g_rowptr[i + 2] = excl + c.x + c.y;
            g_rowptr[i + 3] = excl + c.x + c.y + c.z;
            g_fill[i + 0] = excl;
            g_fill[i + 1] = excl + c.x;
            g_fill[i + 2] = excl + c.x + c.y;
            g_fill[i + 3] = excl + c.x + c.y + c.z;
            g_dis[i + 0] = rsqrtf((float)c.x + 1.0f);
            g_dis[i + 1] = rsqrtf((float)c.y + 1.0f);
            g_dis[i + 2] = rsqrtf((float)c.z + 1.0f);
            g_dis[i + 3] = rsqrtf((float)c.w + 1.0f);
        }
        __syncthreads();
        if (tid == 0) carry_s += tileTot;
        __syncthreads();
    }
    if (tid == 0) g_rowptr[n] = carry_s;
}

__global__ void k_fillcsr(const int* __restrict__ src,
                          const int* __restrict__ dst, int nE) {
    int e = blockIdx.x * blockDim.x + threadIdx.x;
    if (e >= nE) return;
    int d = dst[e];
    int pos = atomicAdd(&g_fill[d], 1);
    g_csrsrc[pos] = src[e];
}

// ---------------------------------------------------------------------------
// GEMM: bufA[n,64] = act(X[n,K]) @ W[K,64]
// Block: 256 threads. Tile 256 nodes x 64 cols; thread = 8 nodes x 8 cols.
// xs stored transposed [k][node] per K-chunk for float4 smem loads.
// ---------------------------------------------------------------------------
template <int K, int KC, bool FROM_BUFB, bool BIASED>
__global__ void __launch_bounds__(256) k_gemm(const float* __restrict__ Xin,
                                              const float* __restrict__ W,
                                              const float* __restrict__ bias,
                                              int n) {
    __shared__ float Ws[K * 64];
    __shared__ float xs[KC * 256];

    const float* X = FROM_BUFB ? g_bufB : Xin;

    for (int i = threadIdx.x; i < K * 16; i += 256)
        ((float4*)Ws)[i] = ((const float4*)W)[i];

    int nodeBase = blockIdx.x * 256;
    int cg = threadIdx.x & 7;   // 8 cols: 8*cg .. 8*cg+7
    int ng = threadIdx.x >> 3;  // 8 nodes: 8*ng .. 8*ng+7

    float4 acc[8][2];
#pragma unroll
    for (int i = 0; i < 8; i++) {
        acc[i][0] = make_float4(0, 0, 0, 0);
        acc[i][1] = make_float4(0, 0, 0, 0);
    }

    int myNode = nodeBase + threadIdx.x;
    for (int k0 = 0; k0 < K; k0 += KC) {
        __syncthreads();
        if (myNode < n) {
            const float4* Xr = (const float4*)(X + (size_t)myNode * K + k0);
#pragma unroll
            for (int kq = 0; kq < KC / 4; kq++) {
                float4 v = Xr[kq];
                if (BIASED) {
                    int kb = k0 + kq * 4;
                    v.x = fmaxf(v.x + bias[kb + 0], 0.0f);
                    v.y = fmaxf(v.y + bias[kb + 1], 0.0f);
                    v.z = fmaxf(v.z + bias[kb + 2], 0.0f);
                    v.w = fmaxf(v.w + bias[kb + 3], 0.0f);
                }
                xs[(kq * 4 + 0) * 256 + threadIdx.x] = v.x;
                xs[(kq * 4 + 1) * 256 + threadIdx.x] = v.y;
                xs[(kq * 4 + 2) * 256 + threadIdx.x] = v.z;
                xs[(kq * 4 + 3) * 256 + threadIdx.x] = v.w;
            }
        } else {
#pragma unroll
            for (int kk = 0; kk < KC; kk++)
                xs[kk * 256 + threadIdx.x] = 0.0f;
        }
        __syncthreads();

#pragma unroll
        for (int k = 0; k < KC; k++) {
            const float4* xr = (const float4*)(xs + k * 256);
            float4 xA = xr[ng * 2], xB = xr[ng * 2 + 1];
            const float4* wr = (const float4*)(Ws + (k0 + k) * 64);
            float4 wA = wr[cg * 2], wB = wr[cg * 2 + 1];
            float xv;
#define GEMM_STEP(i, XV)                                                     \
            xv = (XV);                                                       \
            acc[i][0].x = fmaf(xv, wA.x, acc[i][0].x);                       \
            acc[i][0].y = fmaf(xv, wA.y, acc[i][0].y);                       \
            acc[i][0].z = fmaf(xv, wA.z, acc[i][0].z);                       \
            acc[i][0].w = fmaf(xv, wA.w, acc[i][0].w);                       \
            acc[i][1].x = fmaf(xv, wB.x, acc[i][1].x);                       \
            acc[i][1].y = fmaf(xv, wB.y, acc[i][1].y);                       \
            acc[i][1].z = fmaf(xv, wB.z, acc[i][1].z);                       \
            acc[i][1].w = fmaf(xv, wB.w, acc[i][1].w);
            GEMM_STEP(0, xA.x) GEMM_STEP(1, xA.y) GEMM_STEP(2, xA.z) GEMM_STEP(3, xA.w)
            GEMM_STEP(4, xB.x) GEMM_STEP(5, xB.y) GEMM_STEP(6, xB.z) GEMM_STEP(7, xB.w)
#undef GEMM_STEP
        }
    }

#pragma unroll
    for (int i = 0; i < 8; i++) {
        int node = nodeBase + ng * 8 + i;
        if (node < n) {
            float4* out = (float4*)(g_bufA + (size_t)node * 64);
            out[cg * 2 + 0] = acc[i][0];
            out[cg * 2 + 1] = acc[i][1];
        }
    }
}

// ---------------------------------------------------------------------------
// CSR gather aggregation:
// bufB[i] = dis_i * ( dis_i * bufA[i] + sum_{s in N(i)} dis_s * bufA[s] )
// 16 threads per node (one float4 lane each), no atomics, single write.
// ---------------------------------------------------------------------------
__global__ void k_gather(int n) {
    int idx = blockIdx.x * blockDim.x + threadIdx.x;
    int i = idx >> 4, q = idx & 15;
    if (i >= n) return;
    const float4* A = (const float4*)g_bufA;
    float di = g_dis[i];
    float4 a = A[(size_t)i * 16 + q];
    float4 acc = make_float4(di * a.x, di * a.y, di * a.z, di * a.w);
    int r0 = g_rowptr[i], r1 = g_rowptr[i + 1];
    for (int j = r0; j < r1; j++) {
        int s = g_csrsrc[j];
        float w = g_dis[s];
        float4 v = A[(size_t)s * 16 + q];
        acc.x = fmaf(w, v.x, acc.x);
        acc.y = fmaf(w, v.y, acc.y);
        acc.z = fmaf(w, v.z, acc.z);
        acc.w = fmaf(w, v.w, acc.w);
    }
    acc.x *= di; acc.y *= di; acc.z *= di; acc.w *= di;
    ((float4*)(g_bufB + (size_t)i * 64))[q] = acc;
}

// ---------------------------------------------------------------------------
// pooling: pool[batch[i]] += relu(bufB[i] + b2)
// ---------------------------------------------------------------------------
__global__ void k_pool_acc(const int* __restrict__ batch,
                           const float* __restrict__ b2, int n) {
    int idx = blockIdx.x * blockDim.x + threadIdx.x;
    int i = idx >> 4, q = idx & 15;
    if (i >= n) return;
    int g = batch[i];
    float4 bb = ((const float4*)b2)[q];
    float4 v = ((const float4*)(g_bufB + (size_t)i * 64))[q];
    v.x = fmaxf(v.x + bb.x, 0.0f);
    v.y = fmaxf(v.y + bb.y, 0.0f);
    v.z = fmaxf(v.z + bb.z, 0.0f);
    v.w = fmaxf(v.w + bb.w, 0.0f);
    red_add_v4(g_pool + g * 64 + q * 4, v);
    if (q == 0) atomicAdd(&g_cnt[g], 1.0f);
}

__global__ void k_final(const float* __restrict__ Wf, const float* __restrict__ bf,
                        float* __restrict__ out) {
    int t = threadIdx.x;
    if (t >= N_GRAPHS * 2) return;
    int g = t >> 1, c = t & 1;
    float acc = 0.0f;
#pragma unroll
    for (int j = 0; j < F_HID; j++)
        acc = fmaf(g_pool[g * 64 + j], Wf[j * 2 + c], acc);
    float cnt = fmaxf(g_cnt[g], 1.0f);
    out[g * 2 + c] = acc / cnt + bf[c];
}

// ---------------------------------------------------------------------------
extern "C" void kernel_launch(void* const* d_in, const int* in_sizes, int n_in,
                              void* d_out, int out_size) {
    const float* x    = (const float*)d_in[0];
    const int*   ei   = (const int*)d_in[1];  // [2, E] int32
    const int*   batch= (const int*)d_in[2];
    const float* W1   = (const float*)d_in[3];
    const float* b1   = (const float*)d_in[4];
    const float* W2   = (const float*)d_in[5];
    const float* b2   = (const float*)d_in[6];
    const float* Wf   = (const float*)d_in[7];
    const float* bf   = (const float*)d_in[8];
    float* out = (float*)d_out;

    int n  = in_sizes[0] / F_IN;   // 100000
    int nE = in_sizes[1] / 2;      // 1600000
    const int* src = ei;
    const int* dst = ei + nE;

    const int T = 256;
    int gN   = (n + T - 1) / T;
    int gE   = (nE + T - 1) / T;
    int gN16 = (int)(((size_t)n * 16 + T - 1) / T);
    int gGemm = (n + 255) / 256;

    // CSR build + normalization
    k_zero<<<gN, T>>>(n);
    k_histo<<<gE, T>>>(dst, nE);
    k_scan<<<1, 1024>>>(n);
    k_fillcsr<<<gE, T>>>(src, dst, nE);

    // layer 1
    k_gemm<F_IN, 16, false, false><<<gGemm, T>>>(x, W1, nullptr, n);
    k_gather<<<gN16, T>>>(n);

    // layer 2 (relu+b1 fused into X load)
    k_gemm<F_HID, 32, true, true><<<gGemm, T>>>(nullptr, W2, b1, n);
    k_gather<<<gN16, T>>>(n);

    // pooling (relu+b2 fused) + classifier
    k_pool_acc<<<gN16, T>>>(batch, b2, n);
    k_final<<<1, T>>>(Wf, bf, out);
}